// round 9
// baseline (speedup 1.0000x reference)
#include <cuda_runtime.h>
#include <cuda_bf16.h>
#include <cstdint>

// YOLOv1 loss — non-persistent (wave-staggered) blocks, TMA bulk staging,
// fence-free fp64 RED epilogue + tiny finalize kernel.
// 6272 blocks x 128 threads, one 128-cell tile per block, 30.7KB smem (7/SM).

#define NCELL  (16384 * 7 * 7)       // 802816
#define BLK    128
#define TILE   128                   // cells per block
#define NTILE  (NCELL / TILE)        // 6272
#define TFL    (TILE * 30)           // floats per tensor per tile (3840)
#define TBYTES (TFL * 4)             // 15360 bytes per tensor per tile

__device__ double g_acc[4] = {0.0, 0.0, 0.0, 0.0};   // cls, conf, cwh, noobj

__device__ __forceinline__ uint32_t smem_u32(const void* p) {
    return (uint32_t)__cvta_generic_to_shared(p);
}

__global__ __launch_bounds__(BLK) void yolo_main(const float* __restrict__ P,
                                                 const float* __restrict__ T)
{
    __shared__ __align__(128) float buf[2 * TFL];   // [ P(3840) | T(3840) ]
    __shared__ __align__(8) unsigned long long mbar;
    const int tid = threadIdx.x;
    const float CELL = 1.0f / 7.0f;

    const uint32_t mb = smem_u32(&mbar);
    if (tid == 0) {
        asm volatile("mbarrier.init.shared.b64 [%0], %1;" :: "r"(mb), "r"(1) : "memory");
    }
    __syncthreads();

    if (tid == 0) {
        asm volatile("mbarrier.arrive.expect_tx.shared.b64 _, [%0], %1;"
                     :: "r"(mb), "r"(2 * TBYTES) : "memory");
        const uint32_t d0 = smem_u32(buf);
        const uint32_t d1 = smem_u32(buf + TFL);
        const char* s0 = (const char*)(P + (size_t)blockIdx.x * TFL);
        const char* s1 = (const char*)(T + (size_t)blockIdx.x * TFL);
        asm volatile("cp.async.bulk.shared::cta.global.mbarrier::complete_tx::bytes "
                     "[%0], [%1], %2, [%3];"
                     :: "r"(d0), "l"(s0), "r"(TBYTES), "r"(mb) : "memory");
        asm volatile("cp.async.bulk.shared::cta.global.mbarrier::complete_tx::bytes "
                     "[%0], [%1], %2, [%3];"
                     :: "r"(d1), "l"(s1), "r"(TBYTES), "r"(mb) : "memory");
    }
    // all threads wait for both bulk copies (phase 0)
    {
        uint32_t done;
        asm volatile(
            "{\n\t.reg .pred p;\n\t"
            "mbarrier.try_wait.parity.acquire.cta.shared::cta.b64 p, [%1], %2;\n\t"
            "selp.b32 %0, 1, 0, p;\n\t}"
            : "=r"(done) : "r"(mb), "r"(0) : "memory");
        if (!done) {
            asm volatile(
                "{\n\t.reg .pred P1;\n\t"
                "WL_%=:\n\t"
                "mbarrier.try_wait.parity.acquire.cta.shared::cta.b64 P1, [%0], %1, 0x989680;\n\t"
                "@P1 bra.uni WD_%=;\n\t"
                "bra.uni WL_%=;\n\t"
                "WD_%=:\n\t}"
                :: "r"(mb), "r"(0) : "memory");
        }
    }

    const float* p = buf + tid * 30;
    const float* t = p + TFL;

    const float t0 = t[0], t1 = t[1], t2 = t[2], t3 = t[3], tc = t[4];

    // target corners — faithful to the reference's in-place bug:
    //   xy1 = xy*CELL - wh*0.5 ;  xy2 = xy1*CELL + wh*0.5
    const float twx = t2 * t2, twy = t3 * t3;
    const float tx1 = t0 * CELL - 0.5f * twx;
    const float ty1 = t1 * CELL - 0.5f * twy;
    const float tx2 = tx1 * CELL + 0.5f * twx;
    const float ty2 = ty1 * CELL + 0.5f * twy;
    const float area_t = (tx2 - tx1) * (ty2 - ty1);

    float iou0, iou1;
    #pragma unroll
    for (int b = 0; b < 2; ++b) {
        const float px = p[b * 5 + 0], py = p[b * 5 + 1];
        const float pw = p[b * 5 + 2], ph = p[b * 5 + 3];
        const float pwx = pw * pw, pwy = ph * ph;
        const float x1 = px * CELL - 0.5f * pwx;
        const float y1 = py * CELL - 0.5f * pwy;
        const float x2 = x1 * CELL + 0.5f * pwx;
        const float y2 = y1 * CELL + 0.5f * pwy;
        const float ltx = fmaxf(x1, tx1), lty = fmaxf(y1, ty1);
        const float rbx = fminf(x2, tx2), rby = fminf(y2, ty2);
        const float dx = fmaxf(rbx - ltx, 0.0f);
        const float dy = fmaxf(rby - lty, 0.0f);
        const float inter  = dx * dy;
        const float area_p = (x2 - x1) * (y2 - y1);
        const float v = inter / (area_p + area_t - inter);
        if (b == 0) iou0 = v; else iou1 = v;
    }
    const int b5 = (iou1 > iou0) ? 5 : 0;     // first max wins ties

    // argmax over t[10:30] — order-preserving tree (adjacent pairing keeps
    // index sets contiguous & ordered -> exact first-max semantics, depth 5)
    float av[10]; int ak[10];
    #pragma unroll
    for (int k = 0; k < 10; ++k) {
        const float a = t[10 + 2 * k], b = t[11 + 2 * k];
        const bool g = b > a;
        av[k] = g ? b : a;
        ak[k] = 10 + 2 * k + (g ? 1 : 0);
    }
    #pragma unroll
    for (int k = 0; k < 5; ++k) {
        const bool g = av[2 * k + 1] > av[2 * k];
        av[k] = g ? av[2 * k + 1] : av[2 * k];
        ak[k] = g ? ak[2 * k + 1] : ak[2 * k];
    }
    { const bool g = av[1] > av[0]; av[0] = g ? av[1] : av[0]; ak[0] = g ? ak[1] : ak[0]; }
    { const bool g = av[3] > av[2]; av[2] = g ? av[3] : av[2]; ak[2] = g ? ak[3] : ak[2]; }
    { const bool g = av[2] > av[0]; av[0] = g ? av[2] : av[0]; ak[0] = g ? ak[2] : ak[0]; }
    { const bool g = av[4] > av[0]; av[0] = g ? av[4] : av[0]; ak[0] = g ? ak[4] : ak[0]; }
    const int   kcol = ak[0];
    const float tmax = av[0];     // == t[kcol]

    const bool obj = (tc == 1.0f);
    const bool noo = (tc == 0.0f);

    const float dk = p[kcol]   - tmax;
    const float dc = p[b5 + 4] - t[b5 + 4];
    const float d0 = p[b5 + 0] - t[b5 + 0];
    const float d1 = p[b5 + 1] - t[b5 + 1];
    const float d2 = p[b5 + 2] - t[b5 + 2];
    const float d3 = p[b5 + 3] - t[b5 + 3];
    const float d4 = p[4] - tc;
    const float d9 = p[9] - t[9];

    float ax = 0.0f, ay = 0.0f, az = 0.0f, aw = 0.0f;
    if (obj) {
        ax = dk * dk;                                   // cls
        ay = dc * dc;                                   // conf
        az = d0 * d0 + d1 * d1 + d2 * d2 + d3 * d3;     // center+wh
    }
    if (noo) aw = d4 * d4 + d9 * d9;                    // noobj

    // ---- block reduce ----
    #pragma unroll
    for (int o = 16; o > 0; o >>= 1) {
        ax += __shfl_down_sync(0xffffffffu, ax, o);
        ay += __shfl_down_sync(0xffffffffu, ay, o);
        az += __shfl_down_sync(0xffffffffu, az, o);
        aw += __shfl_down_sync(0xffffffffu, aw, o);
    }
    __shared__ float4 wsum[BLK / 32];
    if ((tid & 31) == 0) wsum[tid >> 5] = make_float4(ax, ay, az, aw);
    __syncthreads();
    if (tid == 0) {
        float4 sv = wsum[0];
        #pragma unroll
        for (int w = 1; w < BLK / 32; ++w) {
            sv.x += wsum[w].x; sv.y += wsum[w].y;
            sv.z += wsum[w].z; sv.w += wsum[w].w;
        }
        // relaxed fp64 reductions — no fence, no return (RED.ADD.F64)
        atomicAdd(&g_acc[0], (double)sv.x);
        atomicAdd(&g_acc[1], (double)sv.y);
        atomicAdd(&g_acc[2], (double)sv.z);
        atomicAdd(&g_acc[3], (double)sv.w);
    }
}

__global__ void yolo_finalize(float* __restrict__ out)
{
    if (threadIdx.x == 0) {
        const float cls = (float)(5.0 * g_acc[0]);   // lambda_coord
        const float cnf = (float)(5.0 * g_acc[1]);
        const float cwh = (float)(5.0 * g_acc[2]);
        const float nob = (float)(0.5 * g_acc[3]);   // lambda_noobj
        out[0] = cls;
        out[1] = cnf;
        out[2] = cwh;
        out[3] = nob + cls + cnf + cwh;              // total
        g_acc[0] = 0.0; g_acc[1] = 0.0;              // reset for next replay
        g_acc[2] = 0.0; g_acc[3] = 0.0;
    }
}

extern "C" void kernel_launch(void* const* d_in, const int* in_sizes, int n_in,
                              void* d_out, int out_size)
{
    const float* P = (const float*)d_in[0];   // predictions [B,S,S,30] fp32
    const float* T = (const float*)d_in[1];   // targets     [B,S,S,30] fp32
    float* out = (float*)d_out;               // [cls, conf, center+wh, total]

    yolo_main<<<NTILE, BLK>>>(P, T);
    yolo_finalize<<<1, 32>>>(out);
}